// round 15
// baseline (speedup 1.0000x reference)
#include <cuda_runtime.h>
#include <cuda_fp16.h>
#include <math.h>
#include <stdint.h>

#define B_     8192
#define OBS_   128
#define LAT_   32
#define NXT_   128
#define E_     8
#define HG_    256
#define H_     256
#define DIN_   (OBS_ + LAT_)   // 160
#define IN1_   (H_ + LAT_)     // 288

typedef unsigned int u32;

// ---------------- device scratch ----------------
__device__ float g_xz [B_ * DIN_];
__device__ float g_h1 [B_ * IN1_];
__device__ float g_h2 [B_ * IN1_];
__device__ float g_coef[B_ * E_];
// fragment-major fp16 weights (bias tile appended), half2-packed words
__device__ u32 g_f0 [4 * 41 * 1024];   // experts now BN=64
__device__ u32 g_f1 [4 * 73 * 1024];
__device__ u32 g_f2 [2 * 73 * 1024];
__device__ u32 g_fg0[6 * 4096];        // gating, BN=256
__device__ u32 g_fg1[9 * 4096];
__device__ u32 g_fg2[9 * 4096];

// ---------------- helpers ----------------
__device__ __forceinline__ uint32_t smem_u32(const void* p) {
    uint32_t a;
    asm("{ .reg .u64 t; cvta.to.shared.u64 t, %1; cvt.u32.u64 %0, t; }" : "=r"(a) : "l"(p));
    return a;
}
#define CP_ASYNC16(dst, src) \
    asm volatile("cp.async.cg.shared.global [%0], [%1], 16;" :: "r"(dst), "l"(src) : "memory")
#define CP_COMMIT() asm volatile("cp.async.commit_group;" ::: "memory")
#define CP_WAIT0()  asm volatile("cp.async.wait_group 0;" ::: "memory")
#define CP_WAIT1()  asm volatile("cp.async.wait_group 1;" ::: "memory")

#define MMA_F16(d, a, b)                                                           \
    asm volatile("mma.sync.aligned.m16n8k16.row.col.f32.f16.f16.f32 "              \
        "{%0,%1,%2,%3}, {%4,%5,%6,%7}, {%8,%9}, {%0,%1,%2,%3};"                    \
        : "+f"((d)[0]), "+f"((d)[1]), "+f"((d)[2]), "+f"((d)[3])                   \
        : "r"((a)[0]), "r"((a)[1]), "r"((a)[2]), "r"((a)[3]),                      \
          "r"((b)[0]), "r"((b)[1]))

#define LDSM_X4(r, addr)                                                           \
    asm volatile("ldmatrix.sync.aligned.m8n8.x4.shared.b16 {%0,%1,%2,%3}, [%4];"   \
        : "=r"((r)[0]), "=r"((r)[1]), "=r"((r)[2]), "=r"((r)[3]) : "r"(addr))

__device__ __forceinline__ u32 pack2(float a, float b) {
    __half2 h = __floats2half2_rn(a, b);
    return *(u32*)&h;
}
__device__ __forceinline__ float elu1(float o) { return (o > 0.f) ? o : expm1f(o); }

// ---------------- fused weight prep + activation pack ----------------
__device__ void wfrag_seg(const float* __restrict__ W, const float* __restrict__ bias,
                          u32* __restrict__ dst, int N, int NT, int NB, int BN,
                          int idx, int stride)
{
    const int CHUNKW = BN * 16;
    const int NTT = NT + 1;
    int total = (N / BN) * NTT * CHUNKW;
    for (int i = idx; i < total; i += stride) {
        int nblk = i / (NTT * CHUNKW);
        int r = i - nblk * NTT * CHUNKW;
        int t = r / CHUNKW;
        int w = r - t * CHUNKW;
        int jj  = w & 1;
        int lid = (w >> 1) & 31;
        int grp = w >> 6;
        int nt = grp & 3, k16 = (grp >> 2) & 1, cg = grp >> 3;
        int col = nblk * BN + cg * 32 + nt * 8 + (lid >> 2);
        int k0  = k16 * 16 + jj * 8 + (lid & 3) * 2;
        float v0, v1;
        if (t < NT) {
            v0 = W[(size_t)(t * 32 + k0) * N + col];
            v1 = W[(size_t)(t * 32 + k0 + 1) * N + col];
        } else {
            v0 = (k0     < NB) ? bias[k0 * N + col]       : 0.f;
            v1 = (k0 + 1 < NB) ? bias[(k0 + 1) * N + col] : 0.f;
        }
        dst[i] = pack2(v0, v1);
    }
}
__global__ void wprep_kernel(const float* x, const float* z,
                             const float* w0, const float* b0,
                             const float* w1, const float* b1,
                             const float* w2, const float* b2,
                             const float* gw0, const float* gb0,
                             const float* gw1, const float* gb1,
                             const float* gw2, const float* gb2)
{
    int idx = blockIdx.x * blockDim.x + threadIdx.x;
    int stride = gridDim.x * blockDim.x;
    // pack xz + z tails
    for (int t = idx; t < B_ * DIN_; t += stride) {
        int b = t / DIN_, c = t - b * DIN_;
        g_xz[t] = (c < OBS_) ? x[b * OBS_ + c] : z[b * LAT_ + (c - OBS_)];
    }
    for (int t = idx; t < B_ * LAT_; t += stride) {
        int b = t / LAT_, c = t - b * LAT_;
        float v = z[t];
        g_h1[b * IN1_ + H_ + c] = v;
        g_h2[b * IN1_ + H_ + c] = v;
    }
    wfrag_seg(w0,  b0,  g_f0,  256, 40, E_,  64, idx, stride);
    wfrag_seg(w1,  b1,  g_f1,  256, 72, E_,  64, idx, stride);
    wfrag_seg(w2,  b2,  g_f2,  128, 72, E_,  64, idx, stride);
    wfrag_seg(gw0, gb0, g_fg0, 256,  5, 1,  256, idx, stride);
    wfrag_seg(gw1, gb1, g_fg1, 256,  8, 1,  256, idx, stride);
    wfrag_seg(gw2, gb2, g_fg2, 256,  8, 1,  256, idx, stride);
}

// ---------------- fused gating MLP + head + softmax (unchanged) ----------------
__global__ __launch_bounds__(256, 1)
void gating_kernel(const float* __restrict__ xz,
                   const u32* __restrict__ f0, const u32* __restrict__ f1,
                   const u32* __restrict__ f2,
                   const float* __restrict__ gw3, const float* __restrict__ gb3)
{
    constexpr int AS = 148;
    extern __shared__ char smem[];
    u32* As = (u32*)smem;
    const int offB = 64 * AS * 4;
    const uint32_t sb = smem_u32(smem);

    const int tid = threadIdx.x, wid = tid >> 5, lid = tid & 31;
    const int g = lid >> 2, tig = lid & 3;
    const int m0 = blockIdx.x * 64;
    const int cgw = wid;
    const uint32_t abase = sb + (((((lid >> 3) & 1) * 8 + (lid & 7)) * AS + (lid >> 4) * 4) << 2);

    for (int i = tid; i < 64 * 96; i += 256) {
        int r = i / 96, w = i - r * 96;
        u32 val;
        if (w < 80) {
            float2 v = *(const float2*)(xz + (size_t)(m0 + r) * DIN_ + 2 * w);
            val = pack2(v.x, v.y);
        } else val = (w == 80) ? pack2(1.f, 0.f) : 0u;
        As[r * AS + w] = val;
    }
    __syncthreads();

    float acc[4][4][4];

    auto run_layer = [&](const u32* Wt, int NTT) {
#pragma unroll
        for (int mt = 0; mt < 4; mt++)
#pragma unroll
            for (int nt = 0; nt < 4; nt++)
#pragma unroll
                for (int q = 0; q < 4; q++) acc[mt][nt][q] = 0.f;
        auto cpB = [&](int t, int buf) {
#pragma unroll
            for (int i = 0; i < 4; i++) {
                int off = tid + 256 * i;
                CP_ASYNC16(sb + offB + buf * 16384 + off * 16, Wt + t * 4096 + off * 4);
            }
            CP_COMMIT();
        };
        cpB(0, 0);
        cpB(1, 1);
        CP_WAIT1();
        __syncthreads();
        for (int t = 0; t < NTT; t++) {
            if (t + 2 < NTT) cpB(t + 2, (t + 2) % 3);
            const u32* Bw = (const u32*)(smem + offB + (t % 3) * 16384);
#pragma unroll
            for (int k16 = 0; k16 < 2; k16++) {
                u32 af[4][4], bf[4][2];
                const uint32_t koff = (t * 16 + k16 * 8) << 2;
#pragma unroll
                for (int mt = 0; mt < 4; mt++)
                    LDSM_X4(af[mt], abase + mt * 16 * AS * 4 + koff);
#pragma unroll
                for (int nt = 0; nt < 4; nt++)
                    *(uint2*)bf[nt] = *(const uint2*)(Bw +
                        ((cgw * 2 + k16) * 4 + nt) * 64 + lid * 2);
#pragma unroll
                for (int mt = 0; mt < 4; mt++)
#pragma unroll
                    for (int nt = 0; nt < 4; nt++)
                        MMA_F16(acc[mt][nt], af[mt], bf[nt]);
            }
            if (t + 2 < NTT) CP_WAIT1(); else CP_WAIT0();
            __syncthreads();
        }
    };

    auto writeback = [&](bool bias_tile) {
#pragma unroll
        for (int mt = 0; mt < 4; mt++) {
            const int r0 = mt * 16 + g;
#pragma unroll
            for (int nt = 0; nt < 4; nt++) {
                const int wv = cgw * 16 + nt * 4 + tig;
                As[r0 * AS + wv]       = pack2(elu1(acc[mt][nt][0]), elu1(acc[mt][nt][1]));
                As[(r0 + 8) * AS + wv] = pack2(elu1(acc[mt][nt][2]), elu1(acc[mt][nt][3]));
            }
        }
        if (bias_tile)
            for (int i = tid; i < 64 * 16; i += 256) {
                int r = i / 16, w = i - r * 16;
                As[r * AS + 128 + w] = (w == 0) ? pack2(1.f, 0.f) : 0u;
            }
        __syncthreads();
    };

    run_layer(f0, 6);  writeback(true);
    run_layer(f1, 9);  writeback(true);
    run_layer(f2, 9);  writeback(false);

    float* gws = (float*)(smem + offB);
    for (int i = tid; i < 256 * 8; i += 256)
        gws[(i >> 3) * 9 + (i & 7)] = gw3[i];
    __syncthreads();
    {
        const int r = tid >> 2, seg = tid & 3;
        float a[8] = {};
        for (int jj = 0; jj < 32; jj++) {
            const int w = seg + 4 * jj;
            u32 pw = As[r * AS + w];
            float2 v = __half22float2(*(__half2*)&pw);
            const float* wr0 = gws + (2 * w) * 9;
#pragma unroll
            for (int e = 0; e < 8; e++) a[e] += v.x * wr0[e] + v.y * wr0[9 + e];
        }
#pragma unroll
        for (int e = 0; e < 8; e++) {
            a[e] += __shfl_xor_sync(0xFFFFFFFFu, a[e], 1);
            a[e] += __shfl_xor_sync(0xFFFFFFFFu, a[e], 2);
        }
        if (seg == 0) {
            float mx = -1e30f;
#pragma unroll
            for (int e = 0; e < 8; e++) { a[e] += gb3[e]; mx = fmaxf(mx, a[e]); }
            float s = 0.f;
#pragma unroll
            for (int e = 0; e < 8; e++) { a[e] = expf(a[e] - mx); s += a[e]; }
            float inv = 1.f / s;
#pragma unroll
            for (int e = 0; e < 8; e++) g_coef[(m0 + r) * E_ + e] = a[e] * inv;
        }
    }
}

// ---------------- expert GEMM: BN=64, MT=1, 3 CTAs/SM ----------------
template<int IN, int TPE, int ACT>
__global__ __launch_bounds__(256, 3)
void expert_kernel(const float* __restrict__ A, int lda,
                   const u32* __restrict__ Wf,
                   const float* __restrict__ coef,
                   float* __restrict__ Cout, int ldc)
{
    constexpr int BN = 64;
    constexpr int NT = E_ * TPE, NTT = NT + 1;
    constexpr int AW = IN / 2, AS = AW + 4;
    constexpr int CHUNKW = BN * 16, BBYTES = CHUNKW * 4;   // 1024 words, 4KB

    extern __shared__ char smem[];
    float* coef_s = (float*)smem;
    u32* As = (u32*)(smem + 2048);
    const int offB = 2048 + 64 * AS * 4;
    const uint32_t sb = smem_u32(smem);

    const int tid = threadIdx.x, wid = tid >> 5, lid = tid & 31;
    const int g = lid >> 2, tig = lid & 3;
    const int m0 = blockIdx.y * 64;
    const int rbase = (wid >> 1) * 16;     // WROWS=4
    const int cgw = wid & 1;               // WCOLS=2
    const u32* Wblk = Wf + (size_t)blockIdx.x * NTT * CHUNKW;
    const uint32_t abase = sb + 2048 +
        (((rbase + ((lid >> 3) & 1) * 8 + (lid & 7)) * AS + (lid >> 4) * 4) << 2);

    for (int i = tid; i < 64 * E_; i += 256) coef_s[i] = coef[m0 * E_ + i];
    for (int i = tid; i < 64 * AW; i += 256) {
        int r = i / AW, w = i - r * AW;
        float2 v = *(const float2*)(A + (size_t)(m0 + r) * lda + 2 * w);
        As[r * AS + w] = pack2(v.x, v.y);
    }

    auto cpB = [&](int t, int buf) {
        CP_ASYNC16(sb + offB + buf * BBYTES + tid * 16, Wblk + t * CHUNKW + tid * 4);
        CP_COMMIT();
    };

    cpB(0, 0);
    cpB(1, 1);
    CP_WAIT1();
    __syncthreads();

    float acc[4][4] = {};

    for (int e = 0; e < E_; e++) {
        float pacc[4][4] = {};
#pragma unroll
        for (int s = 0; s < TPE; s++) {
            const int t = e * TPE + s;
            if (t + 2 < NTT) cpB(t + 2, (t + 2) % 3);
            const u32* Bw = (const u32*)(smem + offB + (t % 3) * BBYTES);
#pragma unroll
            for (int k16 = 0; k16 < 2; k16++) {
                const uint32_t koff = (s * 16 + k16 * 8) << 2;
                u32 af[4], bf[4][2];
                LDSM_X4(af, abase + koff);
#pragma unroll
                for (int nt = 0; nt < 4; nt++)
                    *(uint2*)bf[nt] = *(const uint2*)(Bw +
                        ((cgw * 2 + k16) * 4 + nt) * 64 + lid * 2);
#pragma unroll
                for (int nt = 0; nt < 4; nt++)
                    MMA_F16(pacc[nt], af, bf[nt]);
            }
            if (t + 1 < NTT) {
                if (t + 2 < NTT) CP_WAIT1(); else CP_WAIT0();
                __syncthreads();
            }
        }
        {
            const int r0 = rbase + g;
            float cf0 = coef_s[r0 * E_ + e], cf1 = coef_s[(r0 + 8) * E_ + e];
#pragma unroll
            for (int nt = 0; nt < 4; nt++) {
                acc[nt][0] = fmaf(cf0, pacc[nt][0], acc[nt][0]);
                acc[nt][1] = fmaf(cf0, pacc[nt][1], acc[nt][1]);
                acc[nt][2] = fmaf(cf1, pacc[nt][2], acc[nt][2]);
                acc[nt][3] = fmaf(cf1, pacc[nt][3], acc[nt][3]);
            }
        }
    }

    // bias tile: A-side fragment from coef in registers
    {
        const u32* Bw = (const u32*)(smem + offB + (NT % 3) * BBYTES);
        u32 af[4], bf[4][2];
        const int r0 = rbase + g;
        af[0] = pack2(coef_s[r0 * E_ + 2 * tig], coef_s[r0 * E_ + 2 * tig + 1]);
        af[1] = pack2(coef_s[(r0 + 8) * E_ + 2 * tig], coef_s[(r0 + 8) * E_ + 2 * tig + 1]);
        af[2] = 0u;
        af[3] = 0u;
#pragma unroll
        for (int nt = 0; nt < 4; nt++)
            *(uint2*)bf[nt] = *(const uint2*)(Bw + (cgw * 2 * 4 + nt) * 64 + lid * 2);
#pragma unroll
        for (int nt = 0; nt < 4; nt++)
            MMA_F16(acc[nt], af, bf[nt]);
    }

    const int n0 = blockIdx.x * BN;
    const int r = m0 + rbase + g;
#pragma unroll
    for (int nt = 0; nt < 4; nt++) {
        const int c = n0 + cgw * 32 + nt * 8 + 2 * tig;
        float2 v0, v1;
        v0.x = acc[nt][0]; v0.y = acc[nt][1];
        v1.x = acc[nt][2]; v1.y = acc[nt][3];
        if (ACT == 1) {
            v0.x = elu1(v0.x); v0.y = elu1(v0.y);
            v1.x = elu1(v1.x); v1.y = elu1(v1.y);
        }
        *(float2*)(Cout + (size_t)r * ldc + c)       = v0;
        *(float2*)(Cout + (size_t)(r + 8) * ldc + c) = v1;
    }
}

// ---------------- launch ----------------
extern "C" void kernel_launch(void* const* d_in, const int* in_sizes, int n_in,
                              void* d_out, int out_size)
{
    const float* x   = (const float*)d_in[0];
    const float* z   = (const float*)d_in[1];
    const float* gw0 = (const float*)d_in[2];
    const float* gb0 = (const float*)d_in[3];
    const float* gw1 = (const float*)d_in[4];
    const float* gb1 = (const float*)d_in[5];
    const float* gw2 = (const float*)d_in[6];
    const float* gb2 = (const float*)d_in[7];
    const float* gw3 = (const float*)d_in[8];
    const float* gb3 = (const float*)d_in[9];
    const float* w0  = (const float*)d_in[10];
    const float* b0  = (const float*)d_in[11];
    const float* w1  = (const float*)d_in[12];
    const float* b1  = (const float*)d_in[13];
    const float* w2  = (const float*)d_in[14];
    const float* b2  = (const float*)d_in[15];
    float* out = (float*)d_out;

    float *xz, *h1, *h2, *coef;
    u32 *f0, *f1, *f2, *fg0, *fg1, *fg2;
    cudaGetSymbolAddress((void**)&xz, g_xz);
    cudaGetSymbolAddress((void**)&h1, g_h1);
    cudaGetSymbolAddress((void**)&h2, g_h2);
    cudaGetSymbolAddress((void**)&coef, g_coef);
    cudaGetSymbolAddress((void**)&f0, g_f0);
    cudaGetSymbolAddress((void**)&f1, g_f1);
    cudaGetSymbolAddress((void**)&f2, g_f2);
    cudaGetSymbolAddress((void**)&fg0, g_fg0);
    cudaGetSymbolAddress((void**)&fg1, g_fg1);
    cudaGetSymbolAddress((void**)&fg2, g_fg2);

    const int SMG = 64 * 148 * 4 + 3 * 16384;            // 87040
    const int SM0 = 2048 + 64 * 84 * 4 + 3 * 4096;       // 35840
    const int SM1 = 2048 + 64 * 148 * 4 + 3 * 4096;      // 52224
    cudaFuncSetAttribute(gating_kernel, cudaFuncAttributeMaxDynamicSharedMemorySize, SMG);
    cudaFuncSetAttribute(expert_kernel<DIN_, 5, 1>, cudaFuncAttributeMaxDynamicSharedMemorySize, SM0);
    cudaFuncSetAttribute(expert_kernel<IN1_, 9, 1>, cudaFuncAttributeMaxDynamicSharedMemorySize, SM1);
    cudaFuncSetAttribute(expert_kernel<IN1_, 9, 0>, cudaFuncAttributeMaxDynamicSharedMemorySize, SM1);

    wprep_kernel<<<592, 256>>>(x, z, w0, b0, w1, b1, w2, b2,
                               gw0, gb0, gw1, gb1, gw2, gb2);

    gating_kernel<<<128, 256, SMG>>>(xz, fg0, fg1, fg2, gw3, gb3);

    expert_kernel<DIN_, 5, 1><<<dim3(4, 128), 256, SM0>>>(xz, DIN_, f0, coef, h1, IN1_);
    expert_kernel<IN1_, 9, 1><<<dim3(4, 128), 256, SM1>>>(h1, IN1_, f1, coef, h2, IN1_);
    expert_kernel<IN1_, 9, 0><<<dim3(2, 128), 256, SM1>>>(h2, IN1_, f2, coef, out, NXT_);
}

// round 16
// speedup vs baseline: 1.2484x; 1.2484x over previous
#include <cuda_runtime.h>
#include <cuda_fp16.h>
#include <math.h>
#include <stdint.h>

#define B_     8192
#define OBS_   128
#define LAT_   32
#define NXT_   128
#define E_     8
#define HG_    256
#define H_     256
#define DIN_   (OBS_ + LAT_)   // 160
#define IN1_   (H_ + LAT_)     // 288

typedef unsigned int u32;

// ---------------- device scratch ----------------
__device__ float g_xz [B_ * DIN_];
__device__ float g_h1 [B_ * IN1_];
__device__ float g_h2 [B_ * IN1_];
__device__ float g_coef[B_ * E_];
// fragment-major fp16 weights (bias tile appended), half2-packed words
__device__ u32 g_f0 [2 * 41 * 2048];   // BN=128
__device__ u32 g_f1 [2 * 73 * 2048];   // BN=128
__device__ u32 g_f2 [2 * 73 * 1024];   // BN=64
__device__ u32 g_fg0[6 * 4096];        // gating, BN=256
__device__ u32 g_fg1[9 * 4096];
__device__ u32 g_fg2[9 * 4096];

// ---------------- helpers ----------------
__device__ __forceinline__ uint32_t smem_u32(const void* p) {
    uint32_t a;
    asm("{ .reg .u64 t; cvta.to.shared.u64 t, %1; cvt.u32.u64 %0, t; }" : "=r"(a) : "l"(p));
    return a;
}
#define CP_ASYNC16(dst, src) \
    asm volatile("cp.async.cg.shared.global [%0], [%1], 16;" :: "r"(dst), "l"(src) : "memory")
#define CP_COMMIT() asm volatile("cp.async.commit_group;" ::: "memory")
#define CP_WAIT0()  asm volatile("cp.async.wait_group 0;" ::: "memory")
#define CP_WAIT1()  asm volatile("cp.async.wait_group 1;" ::: "memory")
#define CP_WAIT3()  asm volatile("cp.async.wait_group 3;" ::: "memory")

#define MMA_F16(d, a, b)                                                           \
    asm volatile("mma.sync.aligned.m16n8k16.row.col.f32.f16.f16.f32 "              \
        "{%0,%1,%2,%3}, {%4,%5,%6,%7}, {%8,%9}, {%0,%1,%2,%3};"                    \
        : "+f"((d)[0]), "+f"((d)[1]), "+f"((d)[2]), "+f"((d)[3])                   \
        : "r"((a)[0]), "r"((a)[1]), "r"((a)[2]), "r"((a)[3]),                      \
          "r"((b)[0]), "r"((b)[1]))

#define LDSM_X4(r, addr)                                                           \
    asm volatile("ldmatrix.sync.aligned.m8n8.x4.shared.b16 {%0,%1,%2,%3}, [%4];"   \
        : "=r"((r)[0]), "=r"((r)[1]), "=r"((r)[2]), "=r"((r)[3]) : "r"(addr))

__device__ __forceinline__ u32 pack2(float a, float b) {
    __half2 h = __floats2half2_rn(a, b);
    return *(u32*)&h;
}
__device__ __forceinline__ float elu1(float o) { return (o > 0.f) ? o : expm1f(o); }

// ---------------- fused weight prep + activation pack ----------------
__device__ void wfrag_seg(const float* __restrict__ W, const float* __restrict__ bias,
                          u32* __restrict__ dst, int N, int NT, int NB, int BN,
                          int idx, int stride)
{
    const int CHUNKW = BN * 16;
    const int NTT = NT + 1;
    int total = (N / BN) * NTT * CHUNKW;
    for (int i = idx; i < total; i += stride) {
        int nblk = i / (NTT * CHUNKW);
        int r = i - nblk * NTT * CHUNKW;
        int t = r / CHUNKW;
        int w = r - t * CHUNKW;
        int jj  = w & 1;
        int lid = (w >> 1) & 31;
        int grp = w >> 6;
        int nt = grp & 3, k16 = (grp >> 2) & 1, cg = grp >> 3;
        int col = nblk * BN + cg * 32 + nt * 8 + (lid >> 2);
        int k0  = k16 * 16 + jj * 8 + (lid & 3) * 2;
        float v0, v1;
        if (t < NT) {
            v0 = W[(size_t)(t * 32 + k0) * N + col];
            v1 = W[(size_t)(t * 32 + k0 + 1) * N + col];
        } else {
            v0 = (k0     < NB) ? bias[k0 * N + col]       : 0.f;
            v1 = (k0 + 1 < NB) ? bias[(k0 + 1) * N + col] : 0.f;
        }
        dst[i] = pack2(v0, v1);
    }
}
__global__ void wprep_kernel(const float* x, const float* z,
                             const float* w0, const float* b0,
                             const float* w1, const float* b1,
                             const float* w2, const float* b2,
                             const float* gw0, const float* gb0,
                             const float* gw1, const float* gb1,
                             const float* gw2, const float* gb2)
{
    int idx = blockIdx.x * blockDim.x + threadIdx.x;
    int stride = gridDim.x * blockDim.x;
    for (int t = idx; t < B_ * DIN_; t += stride) {
        int b = t / DIN_, c = t - b * DIN_;
        g_xz[t] = (c < OBS_) ? x[b * OBS_ + c] : z[b * LAT_ + (c - OBS_)];
    }
    for (int t = idx; t < B_ * LAT_; t += stride) {
        int b = t / LAT_, c = t - b * LAT_;
        float v = z[t];
        g_h1[b * IN1_ + H_ + c] = v;
        g_h2[b * IN1_ + H_ + c] = v;
    }
    wfrag_seg(w0,  b0,  g_f0,  256, 40, E_, 128, idx, stride);
    wfrag_seg(w1,  b1,  g_f1,  256, 72, E_, 128, idx, stride);
    wfrag_seg(w2,  b2,  g_f2,  128, 72, E_,  64, idx, stride);
    wfrag_seg(gw0, gb0, g_fg0, 256,  5, 1,  256, idx, stride);
    wfrag_seg(gw1, gb1, g_fg1, 256,  8, 1,  256, idx, stride);
    wfrag_seg(gw2, gb2, g_fg2, 256,  8, 1,  256, idx, stride);
}

// ---------------- fused gating MLP + head + softmax (R14, unchanged) ----------------
__global__ __launch_bounds__(256, 1)
void gating_kernel(const float* __restrict__ xz,
                   const u32* __restrict__ f0, const u32* __restrict__ f1,
                   const u32* __restrict__ f2,
                   const float* __restrict__ gw3, const float* __restrict__ gb3)
{
    constexpr int AS = 148;
    extern __shared__ char smem[];
    u32* As = (u32*)smem;
    const int offB = 64 * AS * 4;
    const uint32_t sb = smem_u32(smem);

    const int tid = threadIdx.x, wid = tid >> 5, lid = tid & 31;
    const int g = lid >> 2, tig = lid & 3;
    const int m0 = blockIdx.x * 64;
    const int cgw = wid;
    const uint32_t abase = sb + (((((lid >> 3) & 1) * 8 + (lid & 7)) * AS + (lid >> 4) * 4) << 2);

    for (int i = tid; i < 64 * 96; i += 256) {
        int r = i / 96, w = i - r * 96;
        u32 val;
        if (w < 80) {
            float2 v = *(const float2*)(xz + (size_t)(m0 + r) * DIN_ + 2 * w);
            val = pack2(v.x, v.y);
        } else val = (w == 80) ? pack2(1.f, 0.f) : 0u;
        As[r * AS + w] = val;
    }
    __syncthreads();

    float acc[4][4][4];

    auto run_layer = [&](const u32* Wt, int NTT) {
#pragma unroll
        for (int mt = 0; mt < 4; mt++)
#pragma unroll
            for (int nt = 0; nt < 4; nt++)
#pragma unroll
                for (int q = 0; q < 4; q++) acc[mt][nt][q] = 0.f;
        auto cpB = [&](int t, int buf) {
#pragma unroll
            for (int i = 0; i < 4; i++) {
                int off = tid + 256 * i;
                CP_ASYNC16(sb + offB + buf * 16384 + off * 16, Wt + t * 4096 + off * 4);
            }
            CP_COMMIT();
        };
        cpB(0, 0);
        cpB(1, 1);
        CP_WAIT1();
        __syncthreads();
        for (int t = 0; t < NTT; t++) {
            if (t + 2 < NTT) cpB(t + 2, (t + 2) % 3);
            const u32* Bw = (const u32*)(smem + offB + (t % 3) * 16384);
#pragma unroll
            for (int k16 = 0; k16 < 2; k16++) {
                u32 af[4][4], bf[4][2];
                const uint32_t koff = (t * 16 + k16 * 8) << 2;
#pragma unroll
                for (int mt = 0; mt < 4; mt++)
                    LDSM_X4(af[mt], abase + mt * 16 * AS * 4 + koff);
#pragma unroll
                for (int nt = 0; nt < 4; nt++)
                    *(uint2*)bf[nt] = *(const uint2*)(Bw +
                        ((cgw * 2 + k16) * 4 + nt) * 64 + lid * 2);
#pragma unroll
                for (int mt = 0; mt < 4; mt++)
#pragma unroll
                    for (int nt = 0; nt < 4; nt++)
                        MMA_F16(acc[mt][nt], af[mt], bf[nt]);
            }
            if (t + 2 < NTT) CP_WAIT1(); else CP_WAIT0();
            __syncthreads();
        }
    };

    auto writeback = [&](bool bias_tile) {
#pragma unroll
        for (int mt = 0; mt < 4; mt++) {
            const int r0 = mt * 16 + g;
#pragma unroll
            for (int nt = 0; nt < 4; nt++) {
                const int wv = cgw * 16 + nt * 4 + tig;
                As[r0 * AS + wv]       = pack2(elu1(acc[mt][nt][0]), elu1(acc[mt][nt][1]));
                As[(r0 + 8) * AS + wv] = pack2(elu1(acc[mt][nt][2]), elu1(acc[mt][nt][3]));
            }
        }
        if (bias_tile)
            for (int i = tid; i < 64 * 16; i += 256) {
                int r = i / 16, w = i - r * 16;
                As[r * AS + 128 + w] = (w == 0) ? pack2(1.f, 0.f) : 0u;
            }
        __syncthreads();
    };

    run_layer(f0, 6);  writeback(true);
    run_layer(f1, 9);  writeback(true);
    run_layer(f2, 9);  writeback(false);

    float* gws = (float*)(smem + offB);
    for (int i = tid; i < 256 * 8; i += 256)
        gws[(i >> 3) * 9 + (i & 7)] = gw3[i];
    __syncthreads();
    {
        const int r = tid >> 2, seg = tid & 3;
        float a[8] = {};
        for (int jj = 0; jj < 32; jj++) {
            const int w = seg + 4 * jj;
            u32 pw = As[r * AS + w];
            float2 v = __half22float2(*(__half2*)&pw);
            const float* wr0 = gws + (2 * w) * 9;
#pragma unroll
            for (int e = 0; e < 8; e++) a[e] += v.x * wr0[e] + v.y * wr0[9 + e];
        }
#pragma unroll
        for (int e = 0; e < 8; e++) {
            a[e] += __shfl_xor_sync(0xFFFFFFFFu, a[e], 1);
            a[e] += __shfl_xor_sync(0xFFFFFFFFu, a[e], 2);
        }
        if (seg == 0) {
            float mx = -1e30f;
#pragma unroll
            for (int e = 0; e < 8; e++) { a[e] += gb3[e]; mx = fmaxf(mx, a[e]); }
            float s = 0.f;
#pragma unroll
            for (int e = 0; e < 8; e++) { a[e] = expf(a[e] - mx); s += a[e]; }
            float inv = 1.f / s;
#pragma unroll
            for (int e = 0; e < 8; e++) g_coef[(m0 + r) * E_ + e] = a[e] * inv;
        }
    }
}

// ---------------- expert GEMM: A resident, per-warp private B rings, NO main-loop barriers ----
template<int IN, int TPE, int BN, int ACT>
__global__ __launch_bounds__(256, 2)
void expert_kernel(const float* __restrict__ A, int lda,
                   const u32* __restrict__ Wf,
                   const float* __restrict__ coef,
                   float* __restrict__ Cout, int ldc)
{
    constexpr int NT = E_ * TPE, NTT = NT + 1;
    constexpr int AW = IN / 2, AS = AW + 4;
    constexpr int CHUNKW = BN * 16;
    constexpr int WCOLS = BN / 32, WROWS = 8 / WCOLS, MT = 64 / (WROWS * 16);

    extern __shared__ char smem[];
    float* coef_s = (float*)smem;
    u32* As = (u32*)(smem + 2048);
    const int offR = 2048 + 64 * AS * 4;        // per-warp rings: 8 x 4 x 2KB
    const uint32_t sb = smem_u32(smem);

    const int tid = threadIdx.x, wid = tid >> 5, lid = tid & 31;
    const int g = lid >> 2, tig = lid & 3;
    const int m0 = blockIdx.y * 64;
    const int rbase = (wid / WCOLS) * (MT * 16);
    const int cgw = wid % WCOLS;
    const u32* Wblk = Wf + (size_t)blockIdx.x * NTT * CHUNKW;
    const uint32_t ring = sb + offR + wid * 8192;
    const uint32_t abase = sb + 2048 +
        (((rbase + ((lid >> 3) & 1) * 8 + (lid & 7)) * AS + (lid >> 4) * 4) << 2);

    for (int i = tid; i < 64 * E_; i += 256) coef_s[i] = coef[m0 * E_ + i];
    for (int i = tid; i < 64 * AW; i += 256) {
        int r = i / AW, w = i - r * AW;
        float2 v = *(const float2*)(A + (size_t)(m0 + r) * lda + 2 * w);
        As[r * AS + w] = pack2(v.x, v.y);
    }

    // per-warp cp of this warp's 512-word slice into private ring slot t&3
    auto cpW = [&](int t) {
        const u32* src = Wblk + (size_t)t * CHUNKW + cgw * 512;
        uint32_t dst = ring + (t & 3) * 2048;
#pragma unroll
        for (int j = 0; j < 4; j++) {
            int w = j * 128 + lid * 4;
            CP_ASYNC16(dst + w * 4, src + w);
        }
        CP_COMMIT();
    };

    cpW(0); cpW(1); cpW(2);
    __syncthreads();   // A + coef visible; rings are warp-private

    float acc[MT][4][4] = {};

    for (int e = 0; e < E_; e++) {
        float pacc[MT][4][4] = {};
#pragma unroll
        for (int s = 0; s < TPE; s++) {
            const int t = e * TPE + s;
            if (t + 3 < NTT) cpW(t + 3);
            else CP_COMMIT();                   // empty group keeps FIFO aligned
            CP_WAIT3();                         // tile t's group complete
            const u32* Bw = (const u32*)(smem + (ring - sb) + (t & 3) * 2048);
#pragma unroll
            for (int k16 = 0; k16 < 2; k16++) {
                const uint32_t koff = (s * 16 + k16 * 8) << 2;
                u32 af[MT][4], bf[4][2];
#pragma unroll
                for (int mt = 0; mt < MT; mt++)
                    LDSM_X4(af[mt], abase + mt * 16 * AS * 4 + koff);
#pragma unroll
                for (int nt = 0; nt < 4; nt++)
                    *(uint2*)bf[nt] = *(const uint2*)(Bw + (k16 * 4 + nt) * 64 + lid * 2);
#pragma unroll
                for (int mt = 0; mt < MT; mt++)
#pragma unroll
                    for (int nt = 0; nt < 4; nt++)
                        MMA_F16(pacc[mt][nt], af[mt], bf[nt]);
            }
        }
#pragma unroll
        for (int mt = 0; mt < MT; mt++) {
            const int r0 = rbase + mt * 16 + g;
            float cf0 = coef_s[r0 * E_ + e], cf1 = coef_s[(r0 + 8) * E_ + e];
#pragma unroll
            for (int nt = 0; nt < 4; nt++) {
                acc[mt][nt][0] = fmaf(cf0, pacc[mt][nt][0], acc[mt][nt][0]);
                acc[mt][nt][1] = fmaf(cf0, pacc[mt][nt][1], acc[mt][nt][1]);
                acc[mt][nt][2] = fmaf(cf1, pacc[mt][nt][2], acc[mt][nt][2]);
                acc[mt][nt][3] = fmaf(cf1, pacc[mt][nt][3], acc[mt][nt][3]);
            }
        }
    }

    // bias tile (t = NT): A-side fragments built from coef in registers
    {
        CP_WAIT0();
        const u32* Bw = (const u32*)(smem + (ring - sb) + (NT & 3) * 2048);
        u32 af[MT][4], bf[4][2];
#pragma unroll
        for (int mt = 0; mt < MT; mt++) {
            const int r0 = rbase + mt * 16 + g;
            af[mt][0] = pack2(coef_s[r0 * E_ + 2 * tig], coef_s[r0 * E_ + 2 * tig + 1]);
            af[mt][1] = pack2(coef_s[(r0 + 8) * E_ + 2 * tig], coef_s[(r0 + 8) * E_ + 2 * tig + 1]);
            af[mt][2] = 0u;
            af[mt][3] = 0u;
        }
#pragma unroll
        for (int nt = 0; nt < 4; nt++)
            *(uint2*)bf[nt] = *(const uint2*)(Bw + nt * 64 + lid * 2);
#pragma unroll
        for (int mt = 0; mt < MT; mt++)
#pragma unroll
            for (int nt = 0; nt < 4; nt++)
                MMA_F16(acc[mt][nt], af[mt], bf[nt]);
    }

    const int n0 = blockIdx.x * BN;
#pragma unroll
    for (int mt = 0; mt < MT; mt++) {
        const int r = m0 + rbase + mt * 16 + g;
#pragma unroll
        for (int nt = 0; nt < 4; nt++) {
            const int c = n0 + cgw * 32 + nt * 8 + 2 * tig;
            float2 v0, v1;
            v0.x = acc[mt][nt][0]; v0.y = acc[mt][nt][1];
            v1.x = acc[mt][nt][2]; v1.y = acc[mt][nt][3];
            if (ACT == 1) {
                v0.x = elu1(v0.x); v0.y = elu1(v0.y);
                v1.x = elu1(v1.x); v1.y = elu1(v1.y);
            }
            *(float2*)(Cout + (size_t)r * ldc + c)       = v0;
            *(float2*)(Cout + (size_t)(r + 8) * ldc + c) = v1;
        }
    }
}

// ---------------- launch ----------------
extern "C" void kernel_launch(void* const* d_in, const int* in_sizes, int n_in,
                              void* d_out, int out_size)
{
    const float* x   = (const float*)d_in[0];
    const float* z   = (const float*)d_in[1];
    const float* gw0 = (const float*)d_in[2];
    const float* gb0 = (const float*)d_in[3];
    const float* gw1 = (const float*)d_in[4];
    const float* gb1 = (const float*)d_in[5];
    const float* gw2 = (const float*)d_in[6];
    const float* gb2 = (const float*)d_in[7];
    const float* gw3 = (const float*)d_in[8];
    const float* gb3 = (const float*)d_in[9];
    const float* w0  = (const float*)d_in[10];
    const float* b0  = (const float*)d_in[11];
    const float* w1  = (const float*)d_in[12];
    const float* b1  = (const float*)d_in[13];
    const float* w2  = (const float*)d_in[14];
    const float* b2  = (const float*)d_in[15];
    float* out = (float*)d_out;

    float *xz, *h1, *h2, *coef;
    u32 *f0, *f1, *f2, *fg0, *fg1, *fg2;
    cudaGetSymbolAddress((void**)&xz, g_xz);
    cudaGetSymbolAddress((void**)&h1, g_h1);
    cudaGetSymbolAddress((void**)&h2, g_h2);
    cudaGetSymbolAddress((void**)&coef, g_coef);
    cudaGetSymbolAddress((void**)&f0, g_f0);
    cudaGetSymbolAddress((void**)&f1, g_f1);
    cudaGetSymbolAddress((void**)&f2, g_f2);
    cudaGetSymbolAddress((void**)&fg0, g_fg0);
    cudaGetSymbolAddress((void**)&fg1, g_fg1);
    cudaGetSymbolAddress((void**)&fg2, g_fg2);

    const int SMG = 64 * 148 * 4 + 3 * 16384;            // 87040
    const int SM0 = 2048 + 64 * 84 * 4 + 8 * 8192;       // 89088
    const int SM1 = 2048 + 64 * 148 * 4 + 8 * 8192;      // 105472
    cudaFuncSetAttribute(gating_kernel, cudaFuncAttributeMaxDynamicSharedMemorySize, SMG);
    cudaFuncSetAttribute(expert_kernel<DIN_, 5, 128, 1>, cudaFuncAttributeMaxDynamicSharedMemorySize, SM0);
    cudaFuncSetAttribute(expert_kernel<IN1_, 9, 128, 1>, cudaFuncAttributeMaxDynamicSharedMemorySize, SM1);
    cudaFuncSetAttribute(expert_kernel<IN1_, 9, 64,  0>, cudaFuncAttributeMaxDynamicSharedMemorySize, SM1);

    wprep_kernel<<<592, 256>>>(x, z, w0, b0, w1, b1, w2, b2,
                               gw0, gb0, gw1, gb1, gw2, gb2);

    gating_kernel<<<128, 256, SMG>>>(xz, fg0, fg1, fg2, gw3, gb3);

    expert_kernel<DIN_, 5, 128, 1><<<dim3(2, 128), 256, SM0>>>(xz, DIN_, f0, coef, h1, IN1_);
    expert_kernel<IN1_, 9, 128, 1><<<dim3(2, 128), 256, SM1>>>(h1, IN1_, f1, coef, h2, IN1_);
    expert_kernel<IN1_, 9, 64,  0><<<dim3(2, 128), 256, SM1>>>(h2, IN1_, f2, coef, out, NXT_);
}